// round 11
// baseline (speedup 1.0000x reference)
#include <cuda_runtime.h>
#include <cstdint>

#define H_IMG 64
#define W_IMG 64
#define CH    128
#define HD    32
#define HEADS 4
#define KS    3
#define DIL   2
#define KK    9
#define PLANE 4096

#define TW 32                  // tile width (pixels)
#define TH 8                   // tile height
#define NTHREADS (TW*TH)       // 256, 1 pixel per thread

#define CPC 4                  // channels per stage
#define NST_K 8                // k stages
#define NST   16               // total stages
#define SH (TH + 4)            // 12 rows
#define SWP 40                 // padded cols: gx in [tileX-4, tileX+36)
#define SEGS 10                // float4 segments per row
#define CELLS (CPC*SH*SEGS)    // 480
#define STAGE_FLOATS (CPC*SH*SWP)   // 1920 (7.5 KB)
#define RING 4
#define RING_BYTES (STAGE_FLOATS*4) // 7680

__device__ __forceinline__ uint32_t s2u(const void* p) {
    return (uint32_t)__cvta_generic_to_shared(p);
}

#define CP_ASYNC(sa, gp, sz) \
    asm volatile("cp.async.cg.shared.global [%0], [%1], 16, %2;\n" \
                 :: "r"(sa), "l"(gp), "r"(sz) : "memory")
#define CP_COMMIT() asm volatile("cp.async.commit_group;\n" ::: "memory")
#define CP_WAIT2()  asm volatile("cp.async.wait_group 2;\n" ::: "memory")

__global__ __launch_bounds__(NTHREADS, 6)
void dilate_attn_kernel(const float* __restrict__ q,
                        const float* __restrict__ k,
                        const float* __restrict__ v,
                        float* __restrict__ out)
{
    __shared__ __align__(16) float ring[RING][STAGE_FLOATS];   // 30 KB

    const int tx  = threadIdx.x;              // 0..31
    const int ty  = threadIdx.y;              // 0..7
    const int tid = ty * TW + tx;

    const int tilesX = W_IMG / TW;            // 2
    const int tileX = (blockIdx.x % tilesX) * TW;
    const int tileY = (blockIdx.x / tilesX) * TH;
    const int head  = blockIdx.y;
    const int b     = blockIdx.z;

    const int x   = tileX + tx;
    const int y   = tileY + ty;
    const int pix = y * W_IMG + x;

    const float scale = 0.1767766952966369f;  // 32^-0.5

    const size_t base = ((size_t)b * CH + head * HD) * PLANE;
    const float* kb = k + base;
    const float* vb = v + base;
    const float* qb = q + base + pix;

    // ---- precompute staging descriptors (loop-invariant across stages) ----
    // cell0: i = tid (always valid); cell1: i = tid+256, valid iff tid < 224
    int goff0, goff1, sz0, sz1;
    uint32_t sa0, sa1;
    {
        const uint32_t sbase = s2u(&ring[0][0]);
#pragma unroll
        for (int cell = 0; cell < 2; cell++) {
            const int i   = tid + cell * NTHREADS;
            const int ch  = i / (SH * SEGS);
            const int rem = i - ch * (SH * SEGS);
            const int row = rem / SEGS;
            const int seg = rem - row * SEGS;
            const int gy  = tileY - 2 + row;
            const int gx  = tileX - 4 + seg * 4;
            const bool inb = (gy >= 0) & (gy < H_IMG) & (gx >= 0) & (gx < W_IMG);
            const int go  = inb ? (ch * PLANE + gy * W_IMG + gx) : 0;
            const int sz  = inb ? 16 : 0;
            const uint32_t sa = sbase + (uint32_t)(ch * (SH * SWP) + row * SWP + seg * 4) * 4u;
            if (cell == 0) { goff0 = go; sz0 = sz; sa0 = sa; }
            else           { goff1 = go; sz1 = sz; sa1 = sa; }
        }
    }
    const bool cell1 = (tid < CELLS - NTHREADS);   // tid < 224 -> warps 0..6

#define ISSUE(srcptr, r) do { \
        CP_ASYNC(sa0 + (r) * RING_BYTES, (srcptr) + goff0, sz0); \
        if (cell1) CP_ASYNC(sa1 + (r) * RING_BYTES, (srcptr) + goff1, sz1); \
        CP_COMMIT(); \
    } while (0)

    // ---- prologue: issue k stages 0,1,2 ----
    ISSUE(kb,             0);
    ISSUE(kb + 1*CPC*PLANE, 1);
    ISSUE(kb + 2*CPC*PLANE, 2);

    float qcur[CPC], qnxt[CPC];
#pragma unroll
    for (int c = 0; c < CPC; c++) qcur[c] = __ldg(qb + (size_t)c * PLANE);
#pragma unroll
    for (int c = 0; c < CPC; c++) qnxt[c] = __ldg(qb + (size_t)(CPC + c) * PLANE);

    float logit[KK];
#pragma unroll
    for (int i = 0; i < KK; i++) logit[i] = 0.f;

    // ================= q.k stages 0..7 =================
#pragma unroll
    for (int s = 0; s < NST_K; s++) {
        CP_WAIT2();
        __syncthreads();

        // issue stage s+3 (k stages 3..7, then v stages 0..2)
        {
            const int sn = s + 3;
            if (sn < NST_K) ISSUE(kb + sn * CPC * PLANE, sn % RING);
            else            ISSUE(vb + (sn - NST_K) * CPC * PLANE, sn % RING);
        }

        // compute stage s
        const float* tb = ring[s % RING];
#pragma unroll
        for (int c = 0; c < CPC; c++) {
            const float* tc = tb + c * (SH * SWP) + ty * SWP + tx + 2;
            const float qc = qcur[c];
#pragma unroll
            for (int ki = 0; ki < KS; ki++)
#pragma unroll
                for (int kj = 0; kj < KS; kj++)
                    logit[ki * KS + kj] = fmaf(qc, tc[(2 * ki) * SWP + 2 * kj],
                                               logit[ki * KS + kj]);
        }

        // rotate q prefetch (distance 2)
#pragma unroll
        for (int c = 0; c < CPC; c++) qcur[c] = qnxt[c];
        if (s + 2 < NST_K) {
#pragma unroll
            for (int c = 0; c < CPC; c++)
                qnxt[c] = __ldg(qb + (size_t)((s + 2) * CPC + c) * PLANE);
        }
    }

    // ================= softmax over 9 taps =================
    {
        float m = -1e30f;
#pragma unroll
        for (int i = 0; i < KK; i++) {
            logit[i] *= scale;
            m = fmaxf(m, logit[i]);
        }
        float ssum = 0.f;
#pragma unroll
        for (int i = 0; i < KK; i++) {
            logit[i] = __expf(logit[i] - m);
            ssum += logit[i];
        }
        const float inv = 1.f / ssum;
#pragma unroll
        for (int i = 0; i < KK; i++) logit[i] *= inv;   // logit[] = weights now
    }

    // ================= a.v stages 8..15 =================
    float* op = out + ((size_t)b * PLANE + pix) * CH + head * HD;

#pragma unroll
    for (int s = NST_K; s < NST; s++) {
        CP_WAIT2();
        __syncthreads();

        {
            const int sn = s + 3;
            if (sn < NST) ISSUE(vb + (sn - NST_K) * CPC * PLANE, sn % RING);
            else          CP_COMMIT();   // empty group: keeps drain count ahead
        }

        const float* tb = ring[s % RING];
        float o[CPC];
#pragma unroll
        for (int c = 0; c < CPC; c++) {
            const float* tc = tb + c * (SH * SWP) + ty * SWP + tx + 2;
            float acc = 0.f;
#pragma unroll
            for (int ki = 0; ki < KS; ki++)
#pragma unroll
                for (int kj = 0; kj < KS; kj++)
                    acc = fmaf(logit[ki * KS + kj], tc[(2 * ki) * SWP + 2 * kj], acc);
            o[c] = acc;
        }

        *reinterpret_cast<float4*>(op + (s - NST_K) * CPC) =
            make_float4(o[0], o[1], o[2], o[3]);
    }
#undef ISSUE
}

extern "C" void kernel_launch(void* const* d_in, const int* in_sizes, int n_in,
                              void* d_out, int out_size)
{
    const float* q = (const float*)d_in[0];
    const float* k = (const float*)d_in[1];
    const float* v = (const float*)d_in[2];
    float* out = (float*)d_out;

    dim3 block(TW, TH);
    dim3 grid((W_IMG / TW) * (H_IMG / TH), HEADS, 16 /*B*/);
    dilate_attn_kernel<<<grid, block>>>(q, k, v, out);
}